// round 1
// baseline (speedup 1.0000x reference)
#include <cuda_runtime.h>

#define NN 100000
#define NE 1600000
#define NG 512

// ---------------- scratch (device globals; no allocations allowed) ----------
__device__ float g_deg[NN];          // after k_prep: 1/deg  (deg = in-degree + 1)
__device__ float g_dinv[NN];         // rsqrt(deg)
__device__ float g_agg1[NN * 80];    // aggregated x (78 used, padded to 80)
__device__ float g_h1[NN * 128];     // relu(gcn1)
__device__ float g_agg2[NN * 128];   // aggregated h1
__device__ float g_sums[NG * 256];   // per-graph sums of h2
__device__ float g_cnt[NG];          // per-graph node counts
__device__ float g_ptab[25 * 8 * 64];// precomputed emb@conv_w table [tok][k][o]
__device__ float g_prot[NG * 64];    // protein features after maxpool

// ---------------- small utility kernels -------------------------------------
__global__ void k_zero() {
    int t = blockIdx.x * blockDim.x + threadIdx.x;
    int stride = gridDim.x * blockDim.x;
    for (int i = t; i < NN; i += stride) g_deg[i] = 0.f;
    for (int i = t; i < NG * 256; i += stride) g_sums[i] = 0.f;
    for (int i = t; i < NG; i += stride) g_cnt[i] = 0.f;
}

__global__ void k_deg(const int* __restrict__ dst) {
    int t = blockIdx.x * blockDim.x + threadIdx.x;
    if (t < NE) atomicAdd(&g_deg[dst[t]], 1.0f);
}

__global__ void k_prep(const int* __restrict__ batch) {
    int t = blockIdx.x * blockDim.x + threadIdx.x;
    if (t < NN) {
        float d = g_deg[t] + 1.0f;
        g_deg[t] = 1.0f / d;        // self-loop coefficient 1/deg
        g_dinv[t] = rsqrtf(d);
        atomicAdd(&g_cnt[batch[t]], 1.0f);
    }
}

// init agg1 with the self-loop term: agg1[i] = x[i] * (1/deg_i); pad cols 78,79 = 0
__global__ void k_init1(const float* __restrict__ x) {
    int t = blockIdx.x * blockDim.x + threadIdx.x;
    if (t < NN * 80) {
        int i = t / 80;
        int j = t - i * 80;
        g_agg1[t] = (j < 78) ? x[i * 78 + j] * g_deg[i] : 0.f;
    }
}

// ---------------- edge scatter, layer 1 (78 floats / edge) ------------------
// warp per edge: lanes 0..18 handle float4 chunks, lane 19 the final float2.
__global__ void k_scatter1(const float* __restrict__ x,
                           const int* __restrict__ src,
                           const int* __restrict__ dst) {
    int w = (blockIdx.x * blockDim.x + threadIdx.x) >> 5;
    int lane = threadIdx.x & 31;
    int nwarp = (gridDim.x * blockDim.x) >> 5;
    for (int e = w; e < NE; e += nwarp) {
        int s = 0, d = 0;
        float nrm = 0.f;
        if (lane == 0) {
            s = src[e];
            d = dst[e];
            nrm = g_dinv[s] * g_dinv[d];
        }
        s = __shfl_sync(0xffffffffu, s, 0);
        d = __shfl_sync(0xffffffffu, d, 0);
        nrm = __shfl_sync(0xffffffffu, nrm, 0);
        if (lane < 19) {
            // x row byte offset = 312*s + 16*lane -> 8-byte aligned: two float2 loads
            const float2* xp = (const float2*)(x + (long)s * 78 + lane * 4);
            float2 a = xp[0], b = xp[1];
            float* p = g_agg1 + (long)d * 80 + lane * 4;   // 16B aligned
            asm volatile("red.global.add.v4.f32 [%0], {%1,%2,%3,%4};"
                         :: "l"(p), "f"(a.x * nrm), "f"(a.y * nrm),
                            "f"(b.x * nrm), "f"(b.y * nrm) : "memory");
        } else if (lane == 19) {
            float2 a = *(const float2*)(x + (long)s * 78 + 76);
            float* p = g_agg1 + (long)d * 80 + 76;          // 8B aligned
            asm volatile("red.global.add.v2.f32 [%0], {%1,%2};"
                         :: "l"(p), "f"(a.x * nrm), "f"(a.y * nrm) : "memory");
        }
    }
}

// ---------------- GEMM1: h1 = relu(agg1 @ W1 + b1), [NN,78]@[78,128] --------
// 128x128 tile, 256 threads, each 4 rows x 16 cols, K in 2 chunks of 40.
__global__ __launch_bounds__(256) void k_gemm1(const float* __restrict__ W1,
                                               const float* __restrict__ b1) {
    __shared__ float sA[128 * 41];
    __shared__ float sB[40 * 128];
    int tid = threadIdx.x;
    int r0 = blockIdx.x * 128;
    int cx = tid & 7, ry = tid >> 3;
    float acc[4][16];
#pragma unroll
    for (int i = 0; i < 4; i++)
#pragma unroll
        for (int j = 0; j < 16; j++) acc[i][j] = 0.f;

#pragma unroll 1
    for (int kc = 0; kc < 80; kc += 40) {
        __syncthreads();
        for (int idx = tid; idx < 40 * 128; idx += 256) {
            int k = idx >> 7, c = idx & 127;
            int gk = kc + k;
            sB[idx] = (gk < 78) ? W1[gk * 128 + c] : 0.f;
        }
        for (int idx = tid; idx < 128 * 40; idx += 256) {
            int r = idx / 40, k = idx - r * 40;
            int row = r0 + r;
            sA[r * 41 + k] = (row < NN) ? g_agg1[(long)row * 80 + kc + k] : 0.f;
        }
        __syncthreads();
#pragma unroll 8
        for (int k = 0; k < 40; k++) {
            float a[4];
#pragma unroll
            for (int i = 0; i < 4; i++) a[i] = sA[(ry * 4 + i) * 41 + k];
            const float4* B4 = (const float4*)(sB + k * 128);
#pragma unroll
            for (int q = 0; q < 4; q++) {
                float4 b = B4[cx * 4 + q];
#pragma unroll
                for (int i = 0; i < 4; i++) {
                    acc[i][q * 4 + 0] += a[i] * b.x;
                    acc[i][q * 4 + 1] += a[i] * b.y;
                    acc[i][q * 4 + 2] += a[i] * b.z;
                    acc[i][q * 4 + 3] += a[i] * b.w;
                }
            }
        }
    }
    int colb = cx * 16;
#pragma unroll
    for (int i = 0; i < 4; i++) {
        int row = r0 + ry * 4 + i;
        if (row < NN) {
#pragma unroll
            for (int q = 0; q < 4; q++) {
                float4 v;
                v.x = fmaxf(acc[i][q * 4 + 0] + b1[colb + q * 4 + 0], 0.f);
                v.y = fmaxf(acc[i][q * 4 + 1] + b1[colb + q * 4 + 1], 0.f);
                v.z = fmaxf(acc[i][q * 4 + 2] + b1[colb + q * 4 + 2], 0.f);
                v.w = fmaxf(acc[i][q * 4 + 3] + b1[colb + q * 4 + 3], 0.f);
                *(float4*)(g_h1 + (long)row * 128 + colb + q * 4) = v;
            }
        }
    }
}

// init agg2 = h1 * (1/deg)
__global__ void k_init2() {
    int t = blockIdx.x * blockDim.x + threadIdx.x;   // one float4 per thread
    if (t < NN * 32) {
        int i = t >> 5;
        float s = g_deg[i];
        float4 v = ((const float4*)g_h1)[t];
        v.x *= s; v.y *= s; v.z *= s; v.w *= s;
        ((float4*)g_agg2)[t] = v;
    }
}

// ---------------- edge scatter, layer 2 (128 floats / edge) -----------------
// warp per edge, each lane one float4 chunk (32*4 = 128).
__global__ void k_scatter2(const int* __restrict__ src,
                           const int* __restrict__ dst) {
    int w = (blockIdx.x * blockDim.x + threadIdx.x) >> 5;
    int lane = threadIdx.x & 31;
    int nwarp = (gridDim.x * blockDim.x) >> 5;
    for (int e = w; e < NE; e += nwarp) {
        int s = 0, d = 0;
        float nrm = 0.f;
        if (lane == 0) {
            s = src[e];
            d = dst[e];
            nrm = g_dinv[s] * g_dinv[d];
        }
        s = __shfl_sync(0xffffffffu, s, 0);
        d = __shfl_sync(0xffffffffu, d, 0);
        nrm = __shfl_sync(0xffffffffu, nrm, 0);
        float4 v = ((const float4*)(g_h1 + (long)s * 128))[lane];
        float* p = g_agg2 + (long)d * 128 + lane * 4;
        asm volatile("red.global.add.v4.f32 [%0], {%1,%2,%3,%4};"
                     :: "l"(p), "f"(v.x * nrm), "f"(v.y * nrm),
                        "f"(v.z * nrm), "f"(v.w * nrm) : "memory");
    }
}

// ---------------- GEMM2 + fused mean-pool epilogue --------------------------
// h2 = relu(agg2 @ W2 + b2); g_sums[batch[row]] += h2[row]  (h2 never stored)
__global__ __launch_bounds__(256) void k_gemm2(const float* __restrict__ W2,
                                               const float* __restrict__ b2,
                                               const int* __restrict__ batch) {
    __shared__ float sA[128 * 33];
    __shared__ float sB[32 * 128];
    int tid = threadIdx.x;
    int r0 = blockIdx.x * 128;
    int cb = blockIdx.y * 128;
    int cx = tid & 7, ry = tid >> 3;
    float acc[4][16];
#pragma unroll
    for (int i = 0; i < 4; i++)
#pragma unroll
        for (int j = 0; j < 16; j++) acc[i][j] = 0.f;

#pragma unroll 1
    for (int kc = 0; kc < 128; kc += 32) {
        __syncthreads();
        for (int idx = tid; idx < 32 * 128; idx += 256) {
            int k = idx >> 7, c = idx & 127;
            sB[idx] = W2[(kc + k) * 256 + cb + c];
        }
        for (int idx = tid; idx < 128 * 32; idx += 256) {
            int r = idx >> 5, k = idx & 31;
            int row = r0 + r;
            sA[r * 33 + k] = (row < NN) ? g_agg2[(long)row * 128 + kc + k] : 0.f;
        }
        __syncthreads();
#pragma unroll 8
        for (int k = 0; k < 32; k++) {
            float a[4];
#pragma unroll
            for (int i = 0; i < 4; i++) a[i] = sA[(ry * 4 + i) * 33 + k];
            const float4* B4 = (const float4*)(sB + k * 128);
#pragma unroll
            for (int q = 0; q < 4; q++) {
                float4 b = B4[cx * 4 + q];
#pragma unroll
                for (int i = 0; i < 4; i++) {
                    acc[i][q * 4 + 0] += a[i] * b.x;
                    acc[i][q * 4 + 1] += a[i] * b.y;
                    acc[i][q * 4 + 2] += a[i] * b.z;
                    acc[i][q * 4 + 3] += a[i] * b.w;
                }
            }
        }
    }
    int colb = cx * 16;
#pragma unroll
    for (int i = 0; i < 4; i++) {
        int row = r0 + ry * 4 + i;
        if (row < NN) {
            int g = batch[row];
            float* base = g_sums + g * 256 + cb + colb;
#pragma unroll
            for (int q = 0; q < 4; q++) {
                float vx = fmaxf(acc[i][q * 4 + 0] + b2[cb + colb + q * 4 + 0], 0.f);
                float vy = fmaxf(acc[i][q * 4 + 1] + b2[cb + colb + q * 4 + 1], 0.f);
                float vz = fmaxf(acc[i][q * 4 + 2] + b2[cb + colb + q * 4 + 2], 0.f);
                float vw = fmaxf(acc[i][q * 4 + 3] + b2[cb + colb + q * 4 + 3], 0.f);
                asm volatile("red.global.add.v4.f32 [%0], {%1,%2,%3,%4};"
                             :: "l"(base + q * 4), "f"(vx), "f"(vy), "f"(vz), "f"(vw)
                             : "memory");
            }
        }
    }
}

// ---------------- protein path ----------------------------------------------
// ptab[tok][k][o] = sum_i emb[tok,i] * conv_w[o,i,k]   (25*8*64 entries)
__global__ void k_ptable(const float* __restrict__ emb,
                         const float* __restrict__ conv_w) {
    int idx = blockIdx.x * blockDim.x + threadIdx.x;
    if (idx < 25 * 8 * 64) {
        int o = idx & 63;
        int k = (idx >> 6) & 7;
        int tok = idx >> 9;
        float s = 0.f;
#pragma unroll 4
        for (int i = 0; i < 128; i++)
            s += emb[tok * 128 + i] * conv_w[o * 1024 + i * 8 + k];
        g_ptab[tok * 512 + k * 64 + o] = s;
    }
}

// conv1d(k=8) + relu + global max pool via the 25-token table.
// grid (NG, 2): block handles one graph x 32 channels. 256 threads.
__global__ __launch_bounds__(256) void k_conv(const int* __restrict__ seq,
                                              const float* __restrict__ conv_b) {
    __shared__ float stab[25 * 8 * 32];
    __shared__ int sseq[1024];
    __shared__ float sred[256];
    int tid = threadIdx.x;
    int b = blockIdx.x;
    int co = blockIdx.y * 32;

    for (int idx = tid; idx < 1024; idx += 256) sseq[idx] = seq[b * 1024 + idx];
    for (int idx = tid; idx < 25 * 8 * 32; idx += 256) {
        int oc = idx & 31;
        int kk = (idx >> 5) & 7;
        int tok = idx >> 8;
        stab[idx] = g_ptab[tok * 512 + kk * 64 + co + oc];
    }
    __syncthreads();

    int oc = tid & 31;
    int l0 = tid >> 5;             // 0..7
    float m = -1e30f;
    for (int l = l0; l < 1017; l += 8) {
        float s = 0.f;
#pragma unroll
        for (int k = 0; k < 8; k++)
            s += stab[(sseq[l + k] * 8 + k) * 32 + oc];
        m = fmaxf(m, s);
    }
    sred[tid] = m;
    __syncthreads();
    if (tid < 32) {
        float mm = sred[tid];
#pragma unroll
        for (int g = 1; g < 8; g++) mm = fmaxf(mm, sred[g * 32 + tid]);
        g_prot[b * 64 + co + tid] = fmaxf(mm + conv_b[co + tid], 0.f);
    }
}

// ---------------- final MLP: [512,320] -> fc1(512) relu -> fc2(1) -----------
__global__ __launch_bounds__(256) void k_final(const float* __restrict__ fc1_w,
                                               const float* __restrict__ fc1_b,
                                               const float* __restrict__ fc2_w,
                                               const float* __restrict__ fc2_b,
                                               float* __restrict__ out) {
    __shared__ float comb[320];
    __shared__ float sred[256];
    int tid = threadIdx.x;
    int b = blockIdx.x;
    float invc = 1.0f / fmaxf(g_cnt[b], 1.0f);
    if (tid < 256) comb[tid] = g_sums[b * 256 + tid] * invc;
    if (tid < 64) comb[256 + tid] = g_prot[b * 64 + tid];
    __syncthreads();

    float part = 0.f;
#pragma unroll
    for (int rep = 0; rep < 2; rep++) {
        int o = tid + rep * 256;
        float acc = fc1_b[o];
#pragma unroll 4
        for (int j = 0; j < 320; j++)
            acc += comb[j] * fc1_w[j * 512 + o];
        part += fmaxf(acc, 0.f) * fc2_w[o];
    }
    sred[tid] = part;
    __syncthreads();
    for (int s = 128; s > 0; s >>= 1) {
        if (tid < s) sred[tid] += sred[tid + s];
        __syncthreads();
    }
    if (tid == 0) out[b] = sred[0] + fc2_b[0];
}

// ---------------- launch ------------------------------------------------------
extern "C" void kernel_launch(void* const* d_in, const int* in_sizes, int n_in,
                              void* d_out, int out_size) {
    const float* x       = (const float*)d_in[0];
    const int*   ei      = (const int*)  d_in[1];   // [2, NE]
    const int*   batch   = (const int*)  d_in[2];
    const int*   seq     = (const int*)  d_in[3];   // [NG, 1024]
    const float* W1      = (const float*)d_in[4];
    const float* b1      = (const float*)d_in[5];
    const float* W2      = (const float*)d_in[6];
    const float* b2      = (const float*)d_in[7];
    const float* emb     = (const float*)d_in[8];
    const float* conv_w  = (const float*)d_in[9];
    const float* conv_b  = (const float*)d_in[10];
    const float* fc1_w   = (const float*)d_in[11];
    const float* fc1_b   = (const float*)d_in[12];
    const float* fc2_w   = (const float*)d_in[13];
    const float* fc2_b   = (const float*)d_in[14];
    float* out = (float*)d_out;

    const int* src = ei;
    const int* dst = ei + NE;

    k_zero<<<512, 256>>>();
    k_deg<<<(NE + 255) / 256, 256>>>(dst);
    k_prep<<<(NN + 255) / 256, 256>>>(batch);
    k_init1<<<(NN * 80 + 255) / 256, 256>>>(x);
    k_scatter1<<<2048, 256>>>(x, src, dst);
    k_gemm1<<<(NN + 127) / 128, 256>>>(W1, b1);
    k_init2<<<(NN * 32 + 255) / 256, 256>>>();
    k_scatter2<<<2048, 256>>>(src, dst);
    {
        dim3 grid((NN + 127) / 128, 2);
        k_gemm2<<<grid, 256>>>(W2, b2, batch);
    }
    k_ptable<<<(25 * 8 * 64 + 255) / 256, 256>>>(emb, conv_w);
    {
        dim3 grid(NG, 2);
        k_conv<<<grid, 256>>>(seq, conv_b);
    }
    k_final<<<NG, 256>>>(fc1_w, fc1_b, fc2_w, fc2_b, out);
}